// round 14
// baseline (speedup 1.0000x reference)
#include <cuda_runtime.h>
#include <cuda_bf16.h>

#define B_ROWS   16384
#define CWIN     10
#define KNEG     10
#define NSCORE   (KNEG + 1)
#define DIM      128
#define VEC      (DIM / 4)          // 32 float4 per row -> 1 per lane
#define ROWS_PER_WARP  2
#define WARPS_PER_BLOCK 8
#define ROWS_PER_BLOCK (ROWS_PER_WARP * WARPS_PER_BLOCK)   // 16
#define NTHREADS 256
#define NBLOCKS  (B_ROWS / ROWS_PER_BLOCK)                 // 1024
#define EPS      1e-9f
#define FULLM    0xffffffffu

// Scratch for deterministic reduction (no allocations allowed).
__device__ float        g_block_partial[NBLOCKS];
__device__ unsigned int g_done_counter = 0u;

__global__ __launch_bounds__(NTHREADS, 4) void cbow_loss_kernel(
    const int*   __restrict__ ctx,      // [B, CWIN]
    const int*   __restrict__ tgt,      // [B]
    const int*   __restrict__ neg,      // [B, KNEG]
    const float* __restrict__ in_emb,   // [VOCAB, DIM]
    const float* __restrict__ out_emb,  // [VOCAB, DIM]
    float*       __restrict__ out)
{
    const int warp = threadIdx.x >> 5;
    const int lane = threadIdx.x & 31;
    const int pair = blockIdx.x * WARPS_PER_BLOCK + warp;   // one row-pair per warp

    const float4* __restrict__ in4  = (const float4*)in_emb;
    const float4* __restrict__ out4 = (const float4*)out_emb;
    const int4*   __restrict__ ctx4 = (const int4*)ctx;     // pair block: 20 ints = 5 int4
    const int4*   __restrict__ neg4 = (const int4*)neg;     // pair block: 20 ints = 5 int4
    const int2*   __restrict__ tgt2 = (const int2*)tgt;     // pair block: 2 ints = 1 int2

    // ---- phase A: ctx indices (5 vector loads), then 20 gathers ----
    union { int4 v[5]; int a[20]; } ci;
#pragma unroll
    for (int q = 0; q < 5; q++)
        ci.v[q] = __ldg(&ctx4[(size_t)pair * 5 + q]);

    float4 a0 = make_float4(0.f, 0.f, 0.f, 0.f);
    float4 a1 = make_float4(0.f, 0.f, 0.f, 0.f);
#pragma unroll
    for (int i = 0; i < CWIN; i++) {
        float4 v0 = __ldg(&in4[(size_t)ci.a[i]        * VEC + lane]);
        float4 v1 = __ldg(&in4[(size_t)ci.a[CWIN + i] * VEC + lane]);
        a0.x += v0.x; a0.y += v0.y; a0.z += v0.z; a0.w += v0.w;
        a1.x += v1.x; a1.y += v1.y; a1.z += v1.z; a1.w += v1.w;
    }
    const float inv = 1.0f / (float)CWIN;
    a0.x *= inv; a0.y *= inv; a0.z *= inv; a0.w *= inv;
    a1.x *= inv; a1.y *= inv; a1.z *= inv; a1.w *= inv;

    // ---- phase B: tgt + neg indices (6 vector loads), then 22 gathers ----
    int2 tp = __ldg(&tgt2[pair]);
    union { int4 v[5]; int a[20]; } ni;
#pragma unroll
    for (int q = 0; q < 5; q++)
        ni.v[q] = __ldg(&neg4[(size_t)pair * 5 + q]);

    float s0[NSCORE], s1[NSCORE];
    {
        float4 v0 = __ldg(&out4[(size_t)tp.x * VEC + lane]);
        float4 v1 = __ldg(&out4[(size_t)tp.y * VEC + lane]);
        s0[0] = a0.x * v0.x + a0.y * v0.y + a0.z * v0.z + a0.w * v0.w;
        s1[0] = a1.x * v1.x + a1.y * v1.y + a1.z * v1.z + a1.w * v1.w;
    }
#pragma unroll
    for (int k = 0; k < KNEG; k++) {
        float4 v0 = __ldg(&out4[(size_t)ni.a[k]        * VEC + lane]);
        float4 v1 = __ldg(&out4[(size_t)ni.a[KNEG + k] * VEC + lane]);
        s0[1 + k] = a0.x * v0.x + a0.y * v0.y + a0.z * v0.z + a0.w * v0.w;
        s1[1 + k] = a1.x * v1.x + a1.y * v1.y + a1.z * v1.z + a1.w * v1.w;
    }

    // ---- warp reductions (butterfly), both rows ----
#pragma unroll
    for (int j = 0; j < NSCORE; j++) {
#pragma unroll
        for (int off = 16; off > 0; off >>= 1) {
            s0[j] += __shfl_xor_sync(FULLM, s0[j], off);
            s1[j] += __shfl_xor_sync(FULLM, s1[j], off);
        }
    }

    // ---- loss terms: lanes 0..10 row0, lanes 16..26 row1 ----
    // pos (j==0): log(sigmoid(+s)+eps) = log(1/(1+e^{-s}) + eps)
    // neg:        log(sigmoid(-s)+eps) = log(1/(1+e^{+s}) + eps)
    float term = 0.f;
    {
        int lj = lane & 15;
        bool hi = (lane >= 16);
        if (lj < NSCORE) {
            float sv = hi ? s1[lj] : s0[lj];
            float x  = (lj == 0) ? -sv : sv;
            term = __logf(__frcp_rn(1.0f + __expf(x)) + EPS);
        }
    }
#pragma unroll
    for (int off = 8; off > 0; off >>= 1)
        term += __shfl_xor_sync(FULLM, term, off);
    term += __shfl_xor_sync(FULLM, term, 16);   // fold row1 into lane 0

    __shared__ float sh[WARPS_PER_BLOCK];
    if (lane == 0) sh[warp] = term;
    __syncthreads();

    __shared__ bool amLast;
    if (threadIdx.x == 0) {
        float t = 0.f;
#pragma unroll
        for (int w = 0; w < WARPS_PER_BLOCK; w++) t += sh[w];
        g_block_partial[blockIdx.x] = t;
        __threadfence();
        unsigned prev = atomicAdd(&g_done_counter, 1u);
        amLast = (prev == NBLOCKS - 1);
    }
    __syncthreads();

    // ---- last block: deterministic final reduction, fixed index order ----
    if (amLast) {
        float t = 0.f;
        for (int i = threadIdx.x; i < NBLOCKS; i += NTHREADS)
            t += __ldcg(&g_block_partial[i]);
#pragma unroll
        for (int off = 16; off > 0; off >>= 1)
            t += __shfl_xor_sync(FULLM, t, off);

        __shared__ float shf[NTHREADS / 32];
        if (lane == 0) shf[warp] = t;
        __syncthreads();
        if (threadIdx.x == 0) {
            float total = 0.f;
#pragma unroll
            for (int w = 0; w < NTHREADS / 32; w++) total += shf[w];
            out[0] = -total / (float)B_ROWS;
            g_done_counter = 0u;   // reset for next graph replay
        }
    }
}

extern "C" void kernel_launch(void* const* d_in, const int* in_sizes, int n_in,
                              void* d_out, int out_size)
{
    const int*   ctx     = (const int*)d_in[0];   // context [B, CWIN]
    const int*   tgt     = (const int*)d_in[1];   // target [B]
    const int*   neg     = (const int*)d_in[2];   // negatives [B, KNEG]
    const float* in_emb  = (const float*)d_in[3]; // [VOCAB, DIM]
    const float* out_emb = (const float*)d_in[4]; // [VOCAB, DIM]
    float*       out     = (float*)d_out;

    cbow_loss_kernel<<<NBLOCKS, NTHREADS>>>(ctx, tgt, neg, in_emb, out_emb, out);
}

// round 15
// speedup vs baseline: 1.0060x; 1.0060x over previous
#include <cuda_runtime.h>
#include <cuda_bf16.h>

#define B_ROWS   16384
#define CWIN     10
#define KNEG     10
#define NSCORE   (KNEG + 1)
#define DIM      128
#define VEC      (DIM / 4)          // 32 float4 per row -> 1 per lane
#define ROWS_PER_WARP  2
#define WARPS_PER_BLOCK 8
#define ROWS_PER_BLOCK (ROWS_PER_WARP * WARPS_PER_BLOCK)   // 16
#define NTHREADS 256
#define NBLOCKS  (B_ROWS / ROWS_PER_BLOCK)                 // 1024
#define EPS      1e-9f
#define FULLM    0xffffffffu

// Scratch for deterministic reduction (no allocations allowed).
__device__ float        g_block_partial[NBLOCKS];
__device__ unsigned int g_done_counter = 0u;

__global__ __launch_bounds__(NTHREADS, 4) void cbow_loss_kernel(
    const int*   __restrict__ ctx,      // [B, CWIN]
    const int*   __restrict__ tgt,      // [B]
    const int*   __restrict__ neg,      // [B, KNEG]
    const float* __restrict__ in_emb,   // [VOCAB, DIM]
    const float* __restrict__ out_emb,  // [VOCAB, DIM]
    float*       __restrict__ out)
{
    const int warp = threadIdx.x >> 5;
    const int lane = threadIdx.x & 31;
    const int pair = blockIdx.x * WARPS_PER_BLOCK + warp;   // one row-pair per warp

    const float4* __restrict__ in4  = (const float4*)in_emb;
    const float4* __restrict__ out4 = (const float4*)out_emb;
    const int4*   __restrict__ ctx4 = (const int4*)ctx;     // pair block: 20 ints = 5 int4
    const int4*   __restrict__ neg4 = (const int4*)neg;     // pair block: 20 ints = 5 int4
    const int2*   __restrict__ tgt2 = (const int2*)tgt;     // pair block: 2 ints = 1 int2

    // ---- phase A: ctx indices (5 vector loads), then 20 gathers ----
    union { int4 v[5]; int a[20]; } ci;
#pragma unroll
    for (int q = 0; q < 5; q++)
        ci.v[q] = __ldg(&ctx4[(size_t)pair * 5 + q]);

    float4 a0 = make_float4(0.f, 0.f, 0.f, 0.f);
    float4 a1 = make_float4(0.f, 0.f, 0.f, 0.f);
#pragma unroll
    for (int i = 0; i < CWIN; i++) {
        float4 v0 = __ldg(&in4[(size_t)ci.a[i]        * VEC + lane]);
        float4 v1 = __ldg(&in4[(size_t)ci.a[CWIN + i] * VEC + lane]);
        a0.x += v0.x; a0.y += v0.y; a0.z += v0.z; a0.w += v0.w;
        a1.x += v1.x; a1.y += v1.y; a1.z += v1.z; a1.w += v1.w;
    }
    const float inv = 1.0f / (float)CWIN;
    a0.x *= inv; a0.y *= inv; a0.z *= inv; a0.w *= inv;
    a1.x *= inv; a1.y *= inv; a1.z *= inv; a1.w *= inv;

    // ---- phase B: tgt + neg indices (6 vector loads), then 22 gathers ----
    int2 tp = __ldg(&tgt2[pair]);
    union { int4 v[5]; int a[20]; } ni;
#pragma unroll
    for (int q = 0; q < 5; q++)
        ni.v[q] = __ldg(&neg4[(size_t)pair * 5 + q]);

    float s0[NSCORE], s1[NSCORE];
    {
        float4 v0 = __ldg(&out4[(size_t)tp.x * VEC + lane]);
        float4 v1 = __ldg(&out4[(size_t)tp.y * VEC + lane]);
        s0[0] = a0.x * v0.x + a0.y * v0.y + a0.z * v0.z + a0.w * v0.w;
        s1[0] = a1.x * v1.x + a1.y * v1.y + a1.z * v1.z + a1.w * v1.w;
    }
#pragma unroll
    for (int k = 0; k < KNEG; k++) {
        float4 v0 = __ldg(&out4[(size_t)ni.a[k]        * VEC + lane]);
        float4 v1 = __ldg(&out4[(size_t)ni.a[KNEG + k] * VEC + lane]);
        s0[1 + k] = a0.x * v0.x + a0.y * v0.y + a0.z * v0.z + a0.w * v0.w;
        s1[1 + k] = a1.x * v1.x + a1.y * v1.y + a1.z * v1.z + a1.w * v1.w;
    }

    // ---- warp reductions (butterfly), both rows ----
#pragma unroll
    for (int j = 0; j < NSCORE; j++) {
#pragma unroll
        for (int off = 16; off > 0; off >>= 1) {
            s0[j] += __shfl_xor_sync(FULLM, s0[j], off);
            s1[j] += __shfl_xor_sync(FULLM, s1[j], off);
        }
    }

    // ---- loss terms: lanes 0..10 row0, lanes 16..26 row1 ----
    // pos (j==0): log(sigmoid(+s)+eps) = log(1/(1+e^{-s}) + eps)
    // neg:        log(sigmoid(-s)+eps) = log(1/(1+e^{+s}) + eps)
    float term = 0.f;
    {
        int lj = lane & 15;
        bool hi = (lane >= 16);
        if (lj < NSCORE) {
            float sv = hi ? s1[lj] : s0[lj];
            float x  = (lj == 0) ? -sv : sv;
            term = __logf(__frcp_rn(1.0f + __expf(x)) + EPS);
        }
    }
#pragma unroll
    for (int off = 8; off > 0; off >>= 1)
        term += __shfl_xor_sync(FULLM, term, off);
    term += __shfl_xor_sync(FULLM, term, 16);   // fold row1 into lane 0

    __shared__ float sh[WARPS_PER_BLOCK];
    if (lane == 0) sh[warp] = term;
    __syncthreads();

    __shared__ bool amLast;
    if (threadIdx.x == 0) {
        float t = 0.f;
#pragma unroll
        for (int w = 0; w < WARPS_PER_BLOCK; w++) t += sh[w];
        g_block_partial[blockIdx.x] = t;
        __threadfence();
        unsigned prev = atomicAdd(&g_done_counter, 1u);
        amLast = (prev == NBLOCKS - 1);
    }
    __syncthreads();

    // ---- last block: deterministic final reduction, fixed index order ----
    if (amLast) {
        float t = 0.f;
        for (int i = threadIdx.x; i < NBLOCKS; i += NTHREADS)
            t += __ldcg(&g_block_partial[i]);
#pragma unroll
        for (int off = 16; off > 0; off >>= 1)
            t += __shfl_xor_sync(FULLM, t, off);

        __shared__ float shf[NTHREADS / 32];
        if (lane == 0) shf[warp] = t;
        __syncthreads();
        if (threadIdx.x == 0) {
            float total = 0.f;
#pragma unroll
            for (int w = 0; w < NTHREADS / 32; w++) total += shf[w];
            out[0] = -total / (float)B_ROWS;
            g_done_counter = 0u;   // reset for next graph replay
        }
    }
}

extern "C" void kernel_launch(void* const* d_in, const int* in_sizes, int n_in,
                              void* d_out, int out_size)
{
    const int*   ctx     = (const int*)d_in[0];   // context [B, CWIN]
    const int*   tgt     = (const int*)d_in[1];   // target [B]
    const int*   neg     = (const int*)d_in[2];   // negatives [B, KNEG]
    const float* in_emb  = (const float*)d_in[3]; // [VOCAB, DIM]
    const float* out_emb = (const float*)d_in[4]; // [VOCAB, DIM]
    float*       out     = (float*)d_out;

    cbow_loss_kernel<<<NBLOCKS, NTHREADS>>>(ctx, tgt, neg, in_emb, out_emb, out);
}

// round 16
// speedup vs baseline: 1.0167x; 1.0107x over previous
#include <cuda_runtime.h>
#include <cuda_bf16.h>

#define B_ROWS   16384
#define CWIN     10
#define KNEG     10
#define NSCORE   (KNEG + 1)
#define DIM      128
#define VEC      (DIM / 4)          // 32 float4 per row -> 1 per lane
#define ROWS_PER_WARP  2
#define WARPS_PER_BLOCK 8
#define ROWS_PER_BLOCK (ROWS_PER_WARP * WARPS_PER_BLOCK)   // 16
#define NTHREADS 256
#define NBLOCKS  (B_ROWS / ROWS_PER_BLOCK)                 // 1024
#define EPS      1e-9f
#define FULLM    0xffffffffu

// Scratch for deterministic reduction (no allocations allowed).
__device__ float        g_block_partial[NBLOCKS];
__device__ unsigned int g_done_counter = 0u;

__global__ __launch_bounds__(NTHREADS, 4) void cbow_loss_kernel(
    const int*   __restrict__ ctx,      // [B, CWIN]
    const int*   __restrict__ tgt,      // [B]
    const int*   __restrict__ neg,      // [B, KNEG]
    const float* __restrict__ in_emb,   // [VOCAB, DIM]
    const float* __restrict__ out_emb,  // [VOCAB, DIM]
    float*       __restrict__ out)
{
    const int warp = threadIdx.x >> 5;
    const int lane = threadIdx.x & 31;
    const int pair = blockIdx.x * WARPS_PER_BLOCK + warp;   // one row-pair per warp

    const float4* __restrict__ in4  = (const float4*)in_emb;
    const float4* __restrict__ out4 = (const float4*)out_emb;
    const int4*   __restrict__ ctx4 = (const int4*)ctx;     // pair block: 20 ints = 5 int4
    const int4*   __restrict__ neg4 = (const int4*)neg;     // pair block: 20 ints = 5 int4
    const int2*   __restrict__ tgt2 = (const int2*)tgt;     // pair block: 2 ints = 1 int2

    // ---- phase A: ctx indices (5 vector loads), then 20 gathers ----
    union { int4 v[5]; int a[20]; } ci;
#pragma unroll
    for (int q = 0; q < 5; q++)
        ci.v[q] = __ldg(&ctx4[(size_t)pair * 5 + q]);

    float4 a0 = make_float4(0.f, 0.f, 0.f, 0.f);
    float4 a1 = make_float4(0.f, 0.f, 0.f, 0.f);
#pragma unroll
    for (int i = 0; i < CWIN; i++) {
        float4 v0 = __ldg(&in4[(size_t)ci.a[i]        * VEC + lane]);
        float4 v1 = __ldg(&in4[(size_t)ci.a[CWIN + i] * VEC + lane]);
        a0.x += v0.x; a0.y += v0.y; a0.z += v0.z; a0.w += v0.w;
        a1.x += v1.x; a1.y += v1.y; a1.z += v1.z; a1.w += v1.w;
    }
    const float inv = 1.0f / (float)CWIN;
    a0.x *= inv; a0.y *= inv; a0.z *= inv; a0.w *= inv;
    a1.x *= inv; a1.y *= inv; a1.z *= inv; a1.w *= inv;

    // ---- phase B: tgt + neg indices (6 vector loads), then 22 gathers ----
    int2 tp = __ldg(&tgt2[pair]);
    union { int4 v[5]; int a[20]; } ni;
#pragma unroll
    for (int q = 0; q < 5; q++)
        ni.v[q] = __ldg(&neg4[(size_t)pair * 5 + q]);

    float s0[NSCORE], s1[NSCORE];
    {
        float4 v0 = __ldg(&out4[(size_t)tp.x * VEC + lane]);
        float4 v1 = __ldg(&out4[(size_t)tp.y * VEC + lane]);
        s0[0] = a0.x * v0.x + a0.y * v0.y + a0.z * v0.z + a0.w * v0.w;
        s1[0] = a1.x * v1.x + a1.y * v1.y + a1.z * v1.z + a1.w * v1.w;
    }
#pragma unroll
    for (int k = 0; k < KNEG; k++) {
        float4 v0 = __ldg(&out4[(size_t)ni.a[k]        * VEC + lane]);
        float4 v1 = __ldg(&out4[(size_t)ni.a[KNEG + k] * VEC + lane]);
        s0[1 + k] = a0.x * v0.x + a0.y * v0.y + a0.z * v0.z + a0.w * v0.w;
        s1[1 + k] = a1.x * v1.x + a1.y * v1.y + a1.z * v1.z + a1.w * v1.w;
    }

    // ---- warp reductions (butterfly), both rows ----
#pragma unroll
    for (int j = 0; j < NSCORE; j++) {
#pragma unroll
        for (int off = 16; off > 0; off >>= 1) {
            s0[j] += __shfl_xor_sync(FULLM, s0[j], off);
            s1[j] += __shfl_xor_sync(FULLM, s1[j], off);
        }
    }

    // ---- loss terms: lanes 0..10 row0, lanes 16..26 row1 ----
    // pos (j==0): log(sigmoid(+s)+eps) = log(1/(1+e^{-s}) + eps)
    // neg:        log(sigmoid(-s)+eps) = log(1/(1+e^{+s}) + eps)
    float term = 0.f;
    {
        int lj = lane & 15;
        bool hi = (lane >= 16);
        if (lj < NSCORE) {
            float sv = hi ? s1[lj] : s0[lj];
            float x  = (lj == 0) ? -sv : sv;
            term = __logf(__frcp_rn(1.0f + __expf(x)) + EPS);
        }
    }
#pragma unroll
    for (int off = 8; off > 0; off >>= 1)
        term += __shfl_xor_sync(FULLM, term, off);
    term += __shfl_xor_sync(FULLM, term, 16);   // fold row1 into lane 0

    __shared__ float sh[WARPS_PER_BLOCK];
    if (lane == 0) sh[warp] = term;
    __syncthreads();

    __shared__ bool amLast;
    if (threadIdx.x == 0) {
        float t = 0.f;
#pragma unroll
        for (int w = 0; w < WARPS_PER_BLOCK; w++) t += sh[w];
        g_block_partial[blockIdx.x] = t;
        __threadfence();
        unsigned prev = atomicAdd(&g_done_counter, 1u);
        amLast = (prev == NBLOCKS - 1);
    }
    __syncthreads();

    // ---- last block: deterministic final reduction, fixed index order ----
    if (amLast) {
        float t = 0.f;
        for (int i = threadIdx.x; i < NBLOCKS; i += NTHREADS)
            t += __ldcg(&g_block_partial[i]);
#pragma unroll
        for (int off = 16; off > 0; off >>= 1)
            t += __shfl_xor_sync(FULLM, t, off);

        __shared__ float shf[NTHREADS / 32];
        if (lane == 0) shf[warp] = t;
        __syncthreads();
        if (threadIdx.x == 0) {
            float total = 0.f;
#pragma unroll
            for (int w = 0; w < NTHREADS / 32; w++) total += shf[w];
            out[0] = -total / (float)B_ROWS;
            g_done_counter = 0u;   // reset for next graph replay
        }
    }
}

extern "C" void kernel_launch(void* const* d_in, const int* in_sizes, int n_in,
                              void* d_out, int out_size)
{
    const int*   ctx     = (const int*)d_in[0];   // context [B, CWIN]
    const int*   tgt     = (const int*)d_in[1];   // target [B]
    const int*   neg     = (const int*)d_in[2];   // negatives [B, KNEG]
    const float* in_emb  = (const float*)d_in[3]; // [VOCAB, DIM]
    const float* out_emb = (const float*)d_in[4]; // [VOCAB, DIM]
    float*       out     = (float*)d_out;

    cbow_loss_kernel<<<NBLOCKS, NTHREADS>>>(ctx, tgt, neg, in_emb, out_emb, out);
}